// round 8
// baseline (speedup 1.0000x reference)
#include <cuda_runtime.h>
#include <math.h>

#define G     1024
#define GM    (G - 1)
#define NA    262144
#define NC    8
#define DT_F  0.1f
#define DEC_F 0.99f
#define SANG  0.6f
#define SLEN  3.0f

// Scratch (static device globals; no allocation anywhere)
__device__ float g_tmp1[NC * G * G];      // horizontal 3-sum, (C,G,G)       32 MB
__device__ float g_box[G * G * NC];       // 3x3 box sum, transposed (G,G,C) 32 MB
__device__ float g_dpher[NA * NC];        // per-agent pheromone delta        8 MB
__device__ int   g_winner[G * G];         // last-writer agent index + 1      4 MB (zero-init)

__device__ __forceinline__ float tanh_ap(float x) {
    float y; asm("tanh.approx.f32 %0, %1;" : "=f"(y) : "f"(x)); return y;
}
__device__ __forceinline__ unsigned cvt_tf32(float f) {
    unsigned r; asm("cvt.rna.tf32.f32 %0, %1;" : "=r"(r) : "f"(f)); return r;
}
__device__ __forceinline__ void mma_tf32(float& d0, float& d1, float& d2, float& d3,
                                         unsigned a0, unsigned a1, unsigned a2, unsigned a3,
                                         unsigned b0, unsigned b1) {
    asm("mma.sync.aligned.m16n8k8.row.col.f32.tf32.tf32.f32 "
        "{%0,%1,%2,%3},{%4,%5,%6,%7},{%8,%9},{%0,%1,%2,%3};"
        : "+f"(d0), "+f"(d1), "+f"(d2), "+f"(d3)
        : "r"(a0), "r"(a1), "r"(a2), "r"(a3), "r"(b0), "r"(b1));
}

// ---------------------------------------------------------------------------
// Pass 1a: horizontal wrapped 3-sum along y.
// ---------------------------------------------------------------------------
__global__ void k_hsum(const float* __restrict__ lat) {
    int t   = blockIdx.x * blockDim.x + threadIdx.x;   // C*G*G/4 threads
    int y0  = (t & 255) << 2;
    int row = t >> 8;                                  // c*G + x
    const float* r = lat + (size_t)row * G;
    float4 m = *(const float4*)(r + y0);
    float lm = __ldg(r + ((y0 + GM) & GM));
    float rp = __ldg(r + ((y0 + 4) & GM));
    float4 o;
    o.x = lm  + m.x + m.y;
    o.y = m.x + m.y + m.z;
    o.z = m.y + m.z + m.w;
    o.w = m.z + m.w + rp;
    *(float4*)(g_tmp1 + (size_t)row * G + y0) = o;
}

// ---------------------------------------------------------------------------
// Pass 1b: vertical wrapped 3-sum along x + transpose to (x,y,c).
// ---------------------------------------------------------------------------
__global__ void k_vsum() {
    int t  = blockIdx.x * blockDim.x + threadIdx.x;    // G*G threads
    int y  = t & GM;
    int x  = t >> 10;
    int xm = (x + GM) & GM;
    int xp = (x + 1) & GM;
    float o[NC];
#pragma unroll
    for (int c = 0; c < NC; c++) {
        const float* p = g_tmp1 + (size_t)c * (G * G);
        o[c] = p[xm * G + y] + p[x * G + y] + p[xp * G + y];
    }
    float4* dst = (float4*)(g_box + (size_t)t * NC);
    dst[0] = make_float4(o[0], o[1], o[2], o[3]);
    dst[1] = make_float4(o[4], o[5], o[6], o[7]);
}

// ---------------------------------------------------------------------------
// Pass 2: per-agent sense + MLP + outputs.
// Layer 1 via 3xTF32 mma.sync (warp handles 32 agents = 2 m16-tiles);
// layer 2 scalar per-thread. All staging through warp-private smem buffer.
// ---------------------------------------------------------------------------
__device__ __forceinline__ void sense24(float px, float py, float vx, float vy,
                                        float* __restrict__ x) {
    const float CA = 0.8253356149096783f;   // cos(0.6)
    const float SA = 0.5646424733950354f;   // sin(0.6)
    float rinv = rsqrtf(vx * vx + vy * vy);
    float c0 = vx * rinv, s0 = vy * rinv;
    float cd[3], sd[3];
    cd[0] = c0;                 sd[0] = s0;
    cd[1] = c0 * CA - s0 * SA;  sd[1] = s0 * CA + c0 * SA;
    cd[2] = c0 * CA + s0 * SA;  sd[2] = s0 * CA - c0 * SA;
#pragma unroll
    for (int s = 0; s < 3; s++) {
        int ix = ((int)rintf(px + SLEN * cd[s])) & GM;
        int iy = ((int)rintf(py + SLEN * sd[s])) & GM;
        const float4* bp = (const float4*)(g_box + ((size_t)(ix * G + iy)) * NC);
        float4 u = bp[0], v = bp[1];
        x[s * 8 + 0] = u.x; x[s * 8 + 1] = u.y; x[s * 8 + 2] = u.z; x[s * 8 + 3] = u.w;
        x[s * 8 + 4] = v.x; x[s * 8 + 5] = v.y; x[s * 8 + 6] = v.z; x[s * 8 + 7] = v.w;
    }
}

#define ROWPAD 68   // buffer row length in floats (>=64, 16B-aligned rows)

__global__ __launch_bounds__(128) void k_agent(
    const float* __restrict__ pos, const float* __restrict__ vel,
    const float* __restrict__ W1,  const float* __restrict__ b1,
    const float* __restrict__ W2,  const float* __restrict__ b2,
    float* __restrict__ out)
{
    __shared__ __align__(16) float sW1[24 * 64];
    __shared__ __align__(16) float sB1[64];
    __shared__ __align__(16) float sW2[64 * 12];
    __shared__ __align__(16) float sB2[12];
    __shared__ __align__(16) float buf[4][32][ROWPAD];  // per-warp x/h staging

    int tid = threadIdx.x;
    for (int i = tid; i < 24 * 64; i += 128) sW1[i] = __ldg(W1 + i);
    if (tid < 64) sB1[tid] = __ldg(b1 + tid);
    for (int i = tid; i < 64 * 12; i += 128) {
        int k = i / 12, m = i - k * 12;
        sW2[i] = (m < 10) ? __ldg(W2 + k * 10 + m) : 0.0f;
    }
    if (tid < 12) sB2[tid] = (tid < 10) ? __ldg(b2 + tid) : 0.0f;
    __syncthreads();

    int w = tid >> 5, l = tid & 31;
    int g = l >> 2, q = l & 3;
    int a = blockIdx.x * 128 + tid;

    float px = pos[a], py = pos[NA + a];
    float vx = vel[a], vy = vel[NA + a];

    float x[24];
    sense24(px, py, vx, vy, x);
    // stage x into warp buffer (row = lane)
#pragma unroll
    for (int i = 0; i < 6; i++)
        *(float4*)&buf[w][l][i * 4] = *(float4*)&x[i * 4];
    __syncwarp();

    // Load A-fragments (hi/lo tf32 split): [mt][kt][4]
    unsigned Ahi[2][3][4], Alo[2][3][4];
#pragma unroll
    for (int mt = 0; mt < 2; mt++) {
#pragma unroll
        for (int kt = 0; kt < 3; kt++) {
            int r0 = mt * 16 + g, r1 = r0 + 8;
            int k0 = kt * 8 + q;
            float f0 = buf[w][r0][k0],     f1 = buf[w][r1][k0];
            float f2 = buf[w][r0][k0 + 4], f3 = buf[w][r1][k0 + 4];
            unsigned h0 = cvt_tf32(f0), h1 = cvt_tf32(f1);
            unsigned h2 = cvt_tf32(f2), h3 = cvt_tf32(f3);
            Ahi[mt][kt][0] = h0; Ahi[mt][kt][1] = h1;
            Ahi[mt][kt][2] = h2; Ahi[mt][kt][3] = h3;
            Alo[mt][kt][0] = cvt_tf32(f0 - __uint_as_float(h0));
            Alo[mt][kt][1] = cvt_tf32(f1 - __uint_as_float(h1));
            Alo[mt][kt][2] = cvt_tf32(f2 - __uint_as_float(h2));
            Alo[mt][kt][3] = cvt_tf32(f3 - __uint_as_float(h3));
        }
    }
    __syncwarp();   // all x reads done before h overwrites buf

    // Layer 1: for each n-tile, 3xTF32 MMA, tanh, store h into buf
#pragma unroll 1
    for (int nt = 0; nt < 8; nt++) {
        int n0 = nt * 8;
        unsigned Bhi[3][2], Blo[3][2];
#pragma unroll
        for (int kt = 0; kt < 3; kt++) {
            float fb0 = sW1[(kt * 8 + q) * 64 + n0 + g];
            float fb1 = sW1[(kt * 8 + q + 4) * 64 + n0 + g];
            unsigned hb0 = cvt_tf32(fb0), hb1 = cvt_tf32(fb1);
            Bhi[kt][0] = hb0; Bhi[kt][1] = hb1;
            Blo[kt][0] = cvt_tf32(fb0 - __uint_as_float(hb0));
            Blo[kt][1] = cvt_tf32(fb1 - __uint_as_float(hb1));
        }
        float bc0 = sB1[n0 + 2 * q], bc1 = sB1[n0 + 2 * q + 1];
#pragma unroll
        for (int mt = 0; mt < 2; mt++) {
            float d0 = bc0, d1 = bc1, d2 = bc0, d3 = bc1;
#pragma unroll
            for (int kt = 0; kt < 3; kt++) {
                mma_tf32(d0, d1, d2, d3,
                         Alo[mt][kt][0], Alo[mt][kt][1], Alo[mt][kt][2], Alo[mt][kt][3],
                         Bhi[kt][0], Bhi[kt][1]);
                mma_tf32(d0, d1, d2, d3,
                         Ahi[mt][kt][0], Ahi[mt][kt][1], Ahi[mt][kt][2], Ahi[mt][kt][3],
                         Blo[kt][0], Blo[kt][1]);
                mma_tf32(d0, d1, d2, d3,
                         Ahi[mt][kt][0], Ahi[mt][kt][1], Ahi[mt][kt][2], Ahi[mt][kt][3],
                         Bhi[kt][0], Bhi[kt][1]);
            }
            int r0 = mt * 16 + g;
            float2 p0 = make_float2(tanh_ap(d0), tanh_ap(d1));
            float2 p1 = make_float2(tanh_ap(d2), tanh_ap(d3));
            *(float2*)&buf[w][r0][n0 + 2 * q]     = p0;
            *(float2*)&buf[w][r0 + 8][n0 + 2 * q] = p1;
        }
    }
    __syncwarp();

    // Layer 2: each thread reads its own h row and does 64x10 scalar FMAs
    float h[64];
#pragma unroll
    for (int i = 0; i < 16; i++)
        *(float4*)&h[i * 4] = *(const float4*)&buf[w][l][i * 4];

    float oc[10];
#pragma unroll
    for (int m = 0; m < 10; m++) oc[m] = sB2[m];
#pragma unroll
    for (int k = 0; k < 64; k++) {
        float hk = h[k];
        const float4* wr = (const float4*)&sW2[k * 12];
        float4 w0 = wr[0], w1 = wr[1], w2 = wr[2];
        oc[0] = fmaf(hk, w0.x, oc[0]); oc[1] = fmaf(hk, w0.y, oc[1]);
        oc[2] = fmaf(hk, w0.z, oc[2]); oc[3] = fmaf(hk, w0.w, oc[3]);
        oc[4] = fmaf(hk, w1.x, oc[4]); oc[5] = fmaf(hk, w1.y, oc[5]);
        oc[6] = fmaf(hk, w1.z, oc[6]); oc[7] = fmaf(hk, w1.w, oc[7]);
        oc[8] = fmaf(hk, w2.x, oc[8]); oc[9] = fmaf(hk, w2.y, oc[9]);
    }

    float npx = px + oc[0] * DT_F, npy = py + oc[1] * DT_F;
    npx -= floorf(npx * (1.0f / G)) * (float)G;
    npy -= floorf(npy * (1.0f / G)) * (float)G;
    out[a] = npx; out[NA + a] = npy;
    out[2 * NA + a] = oc[0]; out[3 * NA + a] = oc[1];

    float4* dp = (float4*)(g_dpher + (size_t)a * NC);
    dp[0] = make_float4(oc[2], oc[3], oc[4], oc[5]);
    dp[1] = make_float4(oc[6], oc[7], oc[8], oc[9]);

    int pix = (int)rintf(px) & GM, piy = (int)rintf(py) & GM;
    atomicMax(&g_winner[pix * G + piy], a + 1);   // "last update wins"
}

// ---------------------------------------------------------------------------
// Pass 3: resolve deposits + decay; 8 cells x 8 channels per thread.
// dpher gathered per-channel (L2-resident). Resets g_winner for replays.
// ---------------------------------------------------------------------------
__global__ void k_update(const float* __restrict__ lat, float* __restrict__ out) {
    int t = blockIdx.x * blockDim.x + threadIdx.x;     // G*G/8 threads
    int4 wa = ((const int4*)g_winner)[2 * t];
    int4 wb = ((const int4*)g_winner)[2 * t + 1];
    int wl[8] = {wa.x, wa.y, wa.z, wa.w, wb.x, wb.y, wb.z, wb.w};
    int any = wl[0] | wl[1] | wl[2] | wl[3] | wl[4] | wl[5] | wl[6] | wl[7];
    if (any) {
        ((int4*)g_winner)[2 * t]     = make_int4(0, 0, 0, 0);
        ((int4*)g_winner)[2 * t + 1] = make_int4(0, 0, 0, 0);
    }

    const float4* l4 = (const float4*)lat;
    float4*       o4 = (float4*)(out + 4 * NA);
#pragma unroll
    for (int c = 0; c < NC; c++) {
        float4 v0 = l4[(size_t)c * (G * G / 4) + 2 * t];
        float4 v1 = l4[(size_t)c * (G * G / 4) + 2 * t + 1];
        float* vv  = (float*)&v0;
        float* vv2 = (float*)&v1;
        if (any) {
#pragma unroll
            for (int u = 0; u < 4; u++)
                if (wl[u]) vv[u] = fmaxf(vv[u] + DT_F * __ldg(g_dpher + (size_t)(wl[u] - 1) * NC + c), 0.0f);
#pragma unroll
            for (int u = 0; u < 4; u++)
                if (wl[u + 4]) vv2[u] = fmaxf(vv2[u] + DT_F * __ldg(g_dpher + (size_t)(wl[u + 4] - 1) * NC + c), 0.0f);
        }
        v0.x *= DEC_F; v0.y *= DEC_F; v0.z *= DEC_F; v0.w *= DEC_F;
        v1.x *= DEC_F; v1.y *= DEC_F; v1.z *= DEC_F; v1.w *= DEC_F;
        o4[(size_t)c * (G * G / 4) + 2 * t]     = v0;
        o4[(size_t)c * (G * G / 4) + 2 * t + 1] = v1;
    }
}

// ---------------------------------------------------------------------------
extern "C" void kernel_launch(void* const* d_in, const int* in_sizes, int n_in,
                              void* d_out, int out_size) {
    const float* pos = (const float*)d_in[0];
    const float* vel = (const float*)d_in[1];
    const float* lat = (const float*)d_in[2];
    const float* W1  = (const float*)d_in[3];
    const float* b1  = (const float*)d_in[4];
    const float* W2  = (const float*)d_in[5];
    const float* b2  = (const float*)d_in[6];
    float* out = (float*)d_out;

    k_hsum  <<<(NC * G * G / 4) / 256, 256>>>(lat);
    k_vsum  <<<(G * G) / 256, 256>>>();
    k_agent <<<NA / 128, 128>>>(pos, vel, W1, b1, W2, b2, out);
    k_update<<<(G * G / 8) / 256, 256>>>(lat, out);
}

// round 9
// speedup vs baseline: 1.1283x; 1.1283x over previous
#include <cuda_runtime.h>
#include <math.h>

#define G     1024
#define GM    (G - 1)
#define NA    262144
#define NC    8
#define DT_F  0.1f
#define DEC_F 0.99f
#define SANG  0.6f
#define SLEN  3.0f

// Scratch (static device globals; no allocation anywhere)
__device__ float g_box[G * G * NC];       // 3x3 box sum, transposed (G,G,C) 32 MB
__device__ float g_dpher[NA * NC];        // per-agent pheromone delta        8 MB
__device__ int   g_winner[G * G];         // last-writer agent index + 1      4 MB (zero-init)

__device__ __forceinline__ float tanh_ap(float x) {
    float y; asm("tanh.approx.f32 %0, %1;" : "=f"(y) : "f"(x)); return y;
}

// ---------------------------------------------------------------------------
// Pass 1 (fused, rolling stencil): wrapped 3x3 box sum, (C,G,G) -> (G,G,C).
// Block = 64-y x 16-x strip. Per x-row: stage raw row slice (66 y x 8 c) in
// smem, y-3-sum into 3-slot ring, then emit box row (x-3-sum of ring) with
// coalesced float2 stores in transposed layout.
// ---------------------------------------------------------------------------
#define YS 64
#define XS 16
__global__ __launch_bounds__(256) void k_box2(const float* __restrict__ lat) {
    __shared__ float raw[66 * 8];          // [y-idx][c]
    __shared__ float ring[3][YS * 8];      // hsum rows for 3 consecutive x
    int y0 = blockIdx.x * YS;
    int x0 = blockIdx.y * XS;
    int tid = threadIdx.x;

#pragma unroll 1
    for (int it = 0; it < XS + 2; it++) {
        int xx = (x0 - 1 + it) & GM;
        // load raw row slice: 8 channels x 66 y (y0-1 .. y0+64 wrapped)
        for (int i = tid; i < 66 * 8; i += 256) {
            int c = i / 66, idx = i - c * 66;
            int yy = (y0 - 1 + idx) & GM;
            raw[idx * 8 + c] = __ldg(lat + ((size_t)c << 20) + ((size_t)xx << 10) + yy);
        }
        __syncthreads();
        // horizontal (y) 3-sum into ring slot
        float* rs = ring[it % 3];
        for (int i = tid; i < YS * 8; i += 256) {
            int j = i >> 3, c = i & 7;
            rs[i] = raw[j * 8 + c] + raw[(j + 1) * 8 + c] + raw[(j + 2) * 8 + c];
        }
        __syncthreads();
        if (it >= 2) {
            int xr = x0 + it - 2;          // output row
            const float* r0 = ring[(it - 2) % 3];
            const float* r1 = ring[(it - 1) % 3];
            const float* r2 = ring[it % 3];
            int i2 = tid * 2;              // 512 floats -> 2 per thread
            float2 v;
            v.x = r0[i2]     + r1[i2]     + r2[i2];
            v.y = r0[i2 + 1] + r1[i2 + 1] + r2[i2 + 1];
            *(float2*)(g_box + ((size_t)xr * G + y0) * NC + i2) = v;
        }
        // next iteration's first __syncthreads orders ring-slot reuse
    }
}

// ---------------------------------------------------------------------------
// Pass 2: per-agent sense + MLP + outputs. 2 agents per thread (shared weight
// loads), layer-2 fused into the layer-1 hidden loop. (R6 verbatim)
// ---------------------------------------------------------------------------
__device__ __forceinline__ void sense24(float px, float py, float vx, float vy,
                                        float* __restrict__ x) {
    const float CA = 0.8253356149096783f;   // cos(0.6)
    const float SA = 0.5646424733950354f;   // sin(0.6)
    float rinv = rsqrtf(vx * vx + vy * vy);
    float c0 = vx * rinv, s0 = vy * rinv;
    float cd[3], sd[3];
    cd[0] = c0;                 sd[0] = s0;
    cd[1] = c0 * CA - s0 * SA;  sd[1] = s0 * CA + c0 * SA;
    cd[2] = c0 * CA + s0 * SA;  sd[2] = s0 * CA - c0 * SA;
#pragma unroll
    for (int s = 0; s < 3; s++) {
        int ix = ((int)rintf(px + SLEN * cd[s])) & GM;
        int iy = ((int)rintf(py + SLEN * sd[s])) & GM;
        const float4* bp = (const float4*)(g_box + ((size_t)(ix * G + iy)) * NC);
        float4 u = bp[0], v = bp[1];
        x[s * 8 + 0] = u.x; x[s * 8 + 1] = u.y; x[s * 8 + 2] = u.z; x[s * 8 + 3] = u.w;
        x[s * 8 + 4] = v.x; x[s * 8 + 5] = v.y; x[s * 8 + 6] = v.z; x[s * 8 + 7] = v.w;
    }
}

__global__ __launch_bounds__(256) void k_agent(
    const float* __restrict__ pos, const float* __restrict__ vel,
    const float* __restrict__ W1,  const float* __restrict__ b1,
    const float* __restrict__ W2,  const float* __restrict__ b2,
    float* __restrict__ out)
{
    __shared__ __align__(16) float sW1[24 * 64];
    __shared__ __align__(16) float sB1[64];
    __shared__ __align__(16) float sW2[64 * 12];   // rows of 10 padded to 12
    __shared__ __align__(16) float sB2[12];

    int tid = threadIdx.x;
    for (int i = tid; i < 24 * 64; i += 256) sW1[i] = __ldg(W1 + i);
    if (tid < 64) sB1[tid] = __ldg(b1 + tid);
    for (int i = tid; i < 64 * 12; i += 256) {
        int k = i / 12, m = i - k * 12;
        sW2[i] = (m < 10) ? __ldg(W2 + k * 10 + m) : 0.0f;
    }
    if (tid < 12) sB2[tid] = (tid < 10) ? __ldg(b2 + tid) : 0.0f;
    __syncthreads();

    int aA = blockIdx.x * 512 + tid;     // two agents per thread
    int aB = aA + 256;

    float pxA = pos[aA], pyA = pos[NA + aA];
    float vxA = vel[aA], vyA = vel[NA + aA];
    float pxB = pos[aB], pyB = pos[NA + aB];
    float vxB = vel[aB], vyB = vel[NA + aB];

    float xA[24], xB[24];
    sense24(pxA, pyA, vxA, vyA, xA);
    sense24(pxB, pyB, vxB, vyB, xB);

    float ocA[10], ocB[10];
#pragma unroll
    for (int m = 0; m < 10; m++) { ocA[m] = sB2[m]; ocB[m] = sB2[m]; }

#pragma unroll
    for (int jq = 0; jq < 16; jq++) {
        float4 b4 = *(const float4*)&sB1[jq * 4];
        float4 aAcc = b4, bAcc = b4;
#pragma unroll
        for (int k = 0; k < 24; k++) {
            float4 w = *(const float4*)&sW1[k * 64 + jq * 4];
            aAcc.x = fmaf(xA[k], w.x, aAcc.x); aAcc.y = fmaf(xA[k], w.y, aAcc.y);
            aAcc.z = fmaf(xA[k], w.z, aAcc.z); aAcc.w = fmaf(xA[k], w.w, aAcc.w);
            bAcc.x = fmaf(xB[k], w.x, bAcc.x); bAcc.y = fmaf(xB[k], w.y, bAcc.y);
            bAcc.z = fmaf(xB[k], w.z, bAcc.z); bAcc.w = fmaf(xB[k], w.w, bAcc.w);
        }
        float hA[4], hB[4];
        hA[0] = tanh_ap(aAcc.x); hA[1] = tanh_ap(aAcc.y);
        hA[2] = tanh_ap(aAcc.z); hA[3] = tanh_ap(aAcc.w);
        hB[0] = tanh_ap(bAcc.x); hB[1] = tanh_ap(bAcc.y);
        hB[2] = tanh_ap(bAcc.z); hB[3] = tanh_ap(bAcc.w);
#pragma unroll
        for (int u = 0; u < 4; u++) {
            int j = jq * 4 + u;
            const float4* wr = (const float4*)&sW2[j * 12];
            float4 w0 = wr[0], w1 = wr[1], w2 = wr[2];
            float ha = hA[u], hb = hB[u];
            ocA[0] = fmaf(ha, w0.x, ocA[0]); ocB[0] = fmaf(hb, w0.x, ocB[0]);
            ocA[1] = fmaf(ha, w0.y, ocA[1]); ocB[1] = fmaf(hb, w0.y, ocB[1]);
            ocA[2] = fmaf(ha, w0.z, ocA[2]); ocB[2] = fmaf(hb, w0.z, ocB[2]);
            ocA[3] = fmaf(ha, w0.w, ocA[3]); ocB[3] = fmaf(hb, w0.w, ocB[3]);
            ocA[4] = fmaf(ha, w1.x, ocA[4]); ocB[4] = fmaf(hb, w1.x, ocB[4]);
            ocA[5] = fmaf(ha, w1.y, ocA[5]); ocB[5] = fmaf(hb, w1.y, ocB[5]);
            ocA[6] = fmaf(ha, w1.z, ocA[6]); ocB[6] = fmaf(hb, w1.z, ocB[6]);
            ocA[7] = fmaf(ha, w1.w, ocA[7]); ocB[7] = fmaf(hb, w1.w, ocB[7]);
            ocA[8] = fmaf(ha, w2.x, ocA[8]); ocB[8] = fmaf(hb, w2.x, ocB[8]);
            ocA[9] = fmaf(ha, w2.y, ocA[9]); ocB[9] = fmaf(hb, w2.y, ocB[9]);
        }
    }

    {
        float npx = pxA + ocA[0] * DT_F, npy = pyA + ocA[1] * DT_F;
        npx -= floorf(npx * (1.0f / G)) * (float)G;
        npy -= floorf(npy * (1.0f / G)) * (float)G;
        out[aA] = npx; out[NA + aA] = npy;
        out[2 * NA + aA] = ocA[0]; out[3 * NA + aA] = ocA[1];
        float4* dp = (float4*)(g_dpher + (size_t)aA * NC);
        dp[0] = make_float4(ocA[2], ocA[3], ocA[4], ocA[5]);
        dp[1] = make_float4(ocA[6], ocA[7], ocA[8], ocA[9]);
        int pix = (int)rintf(pxA) & GM, piy = (int)rintf(pyA) & GM;
        atomicMax(&g_winner[pix * G + piy], aA + 1);
    }
    {
        float npx = pxB + ocB[0] * DT_F, npy = pyB + ocB[1] * DT_F;
        npx -= floorf(npx * (1.0f / G)) * (float)G;
        npy -= floorf(npy * (1.0f / G)) * (float)G;
        out[aB] = npx; out[NA + aB] = npy;
        out[2 * NA + aB] = ocB[0]; out[3 * NA + aB] = ocB[1];
        float4* dp = (float4*)(g_dpher + (size_t)aB * NC);
        dp[0] = make_float4(ocB[2], ocB[3], ocB[4], ocB[5]);
        dp[1] = make_float4(ocB[6], ocB[7], ocB[8], ocB[9]);
        int pix = (int)rintf(pxB) & GM, piy = (int)rintf(pyB) & GM;
        atomicMax(&g_winner[pix * G + piy], aB + 1);
    }
}

// ---------------------------------------------------------------------------
// Pass 3: resolve deposits + decay; 4 cells x 8 channels per thread (float4).
// (R6 verbatim) Resets g_winner so graph replays are identical.
// ---------------------------------------------------------------------------
__global__ void k_update(const float* __restrict__ lat, float* __restrict__ out) {
    int t = blockIdx.x * blockDim.x + threadIdx.x;     // G*G/4 threads
    int4 w4 = ((const int4*)g_winner)[t];
    int wl[4] = {w4.x, w4.y, w4.z, w4.w};
    if (wl[0] | wl[1] | wl[2] | wl[3])
        ((int4*)g_winner)[t] = make_int4(0, 0, 0, 0);

    float dp[4][NC];
#pragma unroll
    for (int u = 0; u < 4; u++) {
        if (wl[u]) {
            const float4* q = (const float4*)(g_dpher + (size_t)(wl[u] - 1) * NC);
            float4 a = q[0], b = q[1];
            dp[u][0] = a.x; dp[u][1] = a.y; dp[u][2] = a.z; dp[u][3] = a.w;
            dp[u][4] = b.x; dp[u][5] = b.y; dp[u][6] = b.z; dp[u][7] = b.w;
        }
    }

    const float4* l4 = (const float4*)lat;
    float4*       o4 = (float4*)(out + 4 * NA);
#pragma unroll
    for (int c = 0; c < NC; c++) {
        float4 v = l4[(size_t)c * (G * G / 4) + t];
        float* vv = (float*)&v;
#pragma unroll
        for (int u = 0; u < 4; u++)
            if (wl[u]) vv[u] = fmaxf(vv[u] + DT_F * dp[u][c], 0.0f);
        v.x *= DEC_F; v.y *= DEC_F; v.z *= DEC_F; v.w *= DEC_F;
        o4[(size_t)c * (G * G / 4) + t] = v;
    }
}

// ---------------------------------------------------------------------------
extern "C" void kernel_launch(void* const* d_in, const int* in_sizes, int n_in,
                              void* d_out, int out_size) {
    const float* pos = (const float*)d_in[0];
    const float* vel = (const float*)d_in[1];
    const float* lat = (const float*)d_in[2];
    const float* W1  = (const float*)d_in[3];
    const float* b1  = (const float*)d_in[4];
    const float* W2  = (const float*)d_in[5];
    const float* b2  = (const float*)d_in[6];
    float* out = (float*)d_out;

    dim3 bgrid(G / YS, G / XS);            // (16, 64) = 1024 blocks
    k_box2  <<<bgrid, 256>>>(lat);
    k_agent <<<NA / 512, 256>>>(pos, vel, W1, b1, W2, b2, out);
    k_update<<<(G * G / 4) / 256, 256>>>(lat, out);
}